// round 6
// baseline (speedup 1.0000x reference)
#include <cuda_runtime.h>
#include <cstddef>

#define DD      512
#define HWV     1024
#define NTOK    16384
#define NBLK    296            // 148 SMs x 2 CTAs -> one wave
#define NBP     320            // padded block rows for pass2 (rows >=296 stay 0)
#define TPB     512
#define TOKTILE 8
#define NTILES  2048           // NTOK / TOKTILE
#define TILEF   (TOKTILE * DD) // floats per smem buffer (4096 = 16KB)

// scratch (device globals are zero-initialized; no allocation allowed)
__device__ float4   g_part4[NBP * DD];   // [blk*512 + d] = {sinv, smui, s1, s2}
__device__ float    g_br[NBLK];
__device__ double   g_cd[DD];
__device__ unsigned g_cnt;               // threadfence-reduction counter (self-resets)

// ---------------------------------------------------------------------------
// Pass 1: single sweep, double-buffered smem x-transpose, one sync per tile,
// pipeline order: [mu/lv LDG] [next-x LDG] [compute] [next-x STS] [sync].
// Thread t -> dg = t&127 (d = 4dg..4dg+3), sub = t>>7 (2-token subset).
// Phase A: thread <-> d row; 2x LDG.128 per row, swizzled scalar STS.
// ---------------------------------------------------------------------------
__global__ __launch_bounds__(TPB, 2)
void club_pass1(const float* __restrict__ x,
                const float* __restrict__ mu,
                const float* __restrict__ lv)
{
    __shared__ float sx[2 * TILEF];        // 32 KB
    const int tid = threadIdx.x;
    const int blk = blockIdx.x;
    const int dg  = tid & 127;
    const int sub = tid >> 7;

    const int gA = tid >> 2;               // d-group for STS (d = tid)
    const int kA = tid & 3;

    float a_sinv[4] = {0,0,0,0};
    float a_smui[4] = {0,0,0,0};
    float a_s1[4]   = {0,0,0,0};
    float a_s2[4]   = {0,0,0,0};
    float a_br = 0.f;

    // ---- prologue: stage tile 'blk' into buffer 0 ----
    {
        const float* xr = x + (size_t)(blk >> 7) * DD * HWV
                            + (size_t)tid * HWV + (blk & 127) * TOKTILE;
        const float4 xa0 = *reinterpret_cast<const float4*>(xr);
        const float4 xa1 = *reinterpret_cast<const float4*>(xr + 4);
        sx[0*DD + 4*(gA ^ 0) + kA] = xa0.x;
        sx[1*DD + 4*(gA ^ 0) + kA] = xa0.y;
        sx[2*DD + 4*(gA ^ 1) + kA] = xa0.z;
        sx[3*DD + 4*(gA ^ 1) + kA] = xa0.w;
        sx[4*DD + 4*(gA ^ 2) + kA] = xa1.x;
        sx[5*DD + 4*(gA ^ 2) + kA] = xa1.y;
        sx[6*DD + 4*(gA ^ 3) + kA] = xa1.z;
        sx[7*DD + 4*(gA ^ 3) + kA] = xa1.w;
    }
    __syncthreads();

    int p = 0;
    for (int t = blk; t < NTILES; t += NBLK) {
        const int nxt = t + NBLK;
        const int t0  = t * TOKTILE;

        // ---- issue mu/lv loads (consumed first in compute) ----
        const float* mup = mu + (size_t)(t0 + sub * 2) * DD + 4 * dg;
        const float* lvp = lv + (size_t)(t0 + sub * 2) * DD + 4 * dg;
        const float4 m0 = *reinterpret_cast<const float4*>(mup);
        const float4 m1 = *reinterpret_cast<const float4*>(mup + DD);
        const float4 l0 = *reinterpret_cast<const float4*>(lvp);
        const float4 l1 = *reinterpret_cast<const float4*>(lvp + DD);

        // ---- issue next-tile x loads (latency hidden under compute) ----
        float4 xn0, xn1;
        if (nxt < NTILES) {
            const float* xr = x + (size_t)(nxt >> 7) * DD * HWV
                                + (size_t)tid * HWV + (nxt & 127) * TOKTILE;
            xn0 = *reinterpret_cast<const float4*>(xr);
            xn1 = *reinterpret_cast<const float4*>(xr + 4);
        }

        // ---- compute on current buffer ----
        {
            const float* cb = sx + p * TILEF;
            #pragma unroll
            for (int j = 0; j < 2; j++) {
                const int ts = sub * 2 + j;
                const float4 xv = *reinterpret_cast<const float4*>(
                    &cb[ts * DD + 4 * (dg ^ ((ts >> 1) & 7))]);
                const float4 mm4 = (j == 0) ? m0 : m1;
                const float4 ll4 = (j == 0) ? l0 : l1;
                float mm[4] = {mm4.x, mm4.y, mm4.z, mm4.w};
                float ll[4] = {ll4.x, ll4.y, ll4.z, ll4.w};
                float xx[4] = {xv.x, xv.y, xv.z, xv.w};
                #pragma unroll
                for (int k = 0; k < 4; k++) {
                    float iv = __expf(-ll[k]);
                    a_sinv[k] += iv;
                    a_smui[k] += mm[k] * iv;
                    a_s1[k]   += xx[k];
                    a_s2[k]   += xx[k] * xx[k];
                    a_br      += (xx[k] - 2.0f * mm[k]) * xx[k] * iv;
                }
            }
        }

        // ---- stage next tile into the other buffer ----
        if (nxt < NTILES) {
            float* sb = sx + (p ^ 1) * TILEF;
            sb[0*DD + 4*(gA ^ 0) + kA] = xn0.x;
            sb[1*DD + 4*(gA ^ 0) + kA] = xn0.y;
            sb[2*DD + 4*(gA ^ 1) + kA] = xn0.z;
            sb[3*DD + 4*(gA ^ 1) + kA] = xn0.w;
            sb[4*DD + 4*(gA ^ 2) + kA] = xn1.x;
            sb[5*DD + 4*(gA ^ 2) + kA] = xn1.y;
            sb[6*DD + 4*(gA ^ 3) + kA] = xn1.z;
            sb[7*DD + 4*(gA ^ 3) + kA] = xn1.w;
        }
        __syncthreads();
        p ^= 1;
    }

    // ---- cross-sub combine via SMEM, coalesced float4 global write ----
    #pragma unroll
    for (int k = 0; k < 4; k++) {
        int base = (sub * 128 + dg) * 16 + k * 4;
        sx[base + 0] = a_sinv[k];
        sx[base + 1] = a_smui[k];
        sx[base + 2] = a_s1[k];
        sx[base + 3] = a_s2[k];
    }
    __syncthreads();
    {
        const int d   = tid;
        const int dg2 = d >> 2, kk = d & 3;
        float4 acc = make_float4(0.f, 0.f, 0.f, 0.f);
        #pragma unroll
        for (int sb = 0; sb < 4; sb++) {
            int base = (sb * 128 + dg2) * 16 + kk * 4;
            acc.x += sx[base + 0];
            acc.y += sx[base + 1];
            acc.z += sx[base + 2];
            acc.w += sx[base + 3];
        }
        g_part4[(size_t)blk * DD + d] = acc;
    }
    __syncthreads();
    sx[tid] = a_br;
    __syncthreads();
    #pragma unroll
    for (int off = 256; off > 0; off >>= 1) {
        if (tid < off) sx[tid] += sx[tid + off];
        __syncthreads();
    }
    if (tid == 0) g_br[blk] = sx[0];
}

// ---------------------------------------------------------------------------
// Pass 2+3 fused: 32 blocks x 512 thr = 512 warps; warp <-> d, lane <-> blk.
// Last-finishing block (threadfence-reduction pattern) does the final double
// tree-sum -> scalar. Counter self-resets for graph replay. Deterministic:
// all sums are fixed-order trees over fixed sets.
// ---------------------------------------------------------------------------
__global__ void club_pass23(float* __restrict__ out)
{
    const int tid  = threadIdx.x;
    const int w    = tid >> 5;
    const int lane = tid & 31;
    const int d    = blockIdx.x * 16 + w;

    float4 acc = make_float4(0.f, 0.f, 0.f, 0.f);
    #pragma unroll
    for (int k = 0; k < NBP / 32; k++) {
        float4 v = g_part4[(size_t)(k * 32 + lane) * DD + d];
        acc.x += v.x; acc.y += v.y; acc.z += v.z; acc.w += v.w;
    }
    #pragma unroll
    for (int off = 16; off > 0; off >>= 1) {
        acc.x += __shfl_xor_sync(0xFFFFFFFFu, acc.x, off);
        acc.y += __shfl_xor_sync(0xFFFFFFFFu, acc.y, off);
        acc.z += __shfl_xor_sync(0xFFFFFFFFu, acc.z, off);
        acc.w += __shfl_xor_sync(0xFFFFFFFFu, acc.w, off);
    }
    if (lane == 0) {
        double m1 = (double)acc.z / (double)NTOK;
        double m2 = (double)acc.w / (double)NTOK;
        g_cd[d] = -(m2 * (double)acc.x) + 2.0 * m1 * (double)acc.y;
        __threadfence();                       // publish before counting
    }
    __syncthreads();

    __shared__ bool amLast;
    if (tid == 0) amLast = (atomicAdd(&g_cnt, 1u) == 31u);
    __syncthreads();

    if (amLast) {
        if (tid == 0) __threadfence();
        __syncthreads();
        __shared__ double sd[512];
        double v = __ldcg(&g_cd[tid]);
        if (tid < NBLK) v += (double)__ldcg(&g_br[tid]);
        sd[tid] = v;
        __syncthreads();
        #pragma unroll
        for (int off = 256; off > 0; off >>= 1) {
            if (tid < off) sd[tid] += sd[tid + off];
            __syncthreads();
        }
        if (tid == 0) {
            out[0] = (float)(-0.5 / (double)NTOK * sd[0]);
            g_cnt = 0;                         // reset for next graph replay
        }
    }
}

// ---------------------------------------------------------------------------
extern "C" void kernel_launch(void* const* d_in, const int* in_sizes, int n_in,
                              void* d_out, int out_size)
{
    (void)in_sizes; (void)n_in; (void)out_size;
    const float* x  = (const float*)d_in[0];
    const float* mu = (const float*)d_in[1];
    const float* lv = (const float*)d_in[2];
    float* out = (float*)d_out;

    club_pass1<<<NBLK, TPB>>>(x, mu, lv);
    club_pass23<<<32, TPB>>>(out);
}

// round 7
// speedup vs baseline: 1.0557x; 1.0557x over previous
#include <cuda_runtime.h>
#include <cstddef>

#define DD      512
#define HWV     1024
#define NTOK    16384
#define NBLK    296            // 148 SMs x 2 CTAs -> one wave
#define NBP     320            // padded block rows for pass2 (rows >=296 stay 0)
#define TPB     512
#define TOKTILE 8
#define NTILES  2048           // NTOK / TOKTILE
#define TILEF   (TOKTILE * DD) // floats per smem buffer (4096 = 16KB)

// scratch (device globals are zero-initialized; no allocation allowed)
// TRANSPOSED layout: [d * NBP + blk] -> pass23 warp reads are coalesced.
__device__ float4   g_part4[DD * NBP];
__device__ float    g_br[NBLK];
__device__ double   g_cd[DD];
__device__ unsigned g_cnt;               // threadfence-reduction counter (self-resets)

// ---------------------------------------------------------------------------
// Pass 1: single sweep, double-buffered smem x-transpose, one sync per tile,
// pipeline order: [mu/lv LDG] [next-x LDG] [compute] [next-x STS] [sync].
// Thread t -> dg = t&127 (d = 4dg..4dg+3), sub = t>>7 (2-token subset).
// ---------------------------------------------------------------------------
__global__ __launch_bounds__(TPB, 2)
void club_pass1(const float* __restrict__ x,
                const float* __restrict__ mu,
                const float* __restrict__ lv)
{
    __shared__ float sx[2 * TILEF];        // 32 KB
    const int tid = threadIdx.x;
    const int blk = blockIdx.x;
    const int dg  = tid & 127;
    const int sub = tid >> 7;

    const int gA = tid >> 2;               // d-group for STS (d = tid)
    const int kA = tid & 3;

    float a_sinv[4] = {0,0,0,0};
    float a_smui[4] = {0,0,0,0};
    float a_s1[4]   = {0,0,0,0};
    float a_s2[4]   = {0,0,0,0};
    float a_br = 0.f;

    // ---- prologue: stage tile 'blk' into buffer 0 ----
    {
        const float* xr = x + (size_t)(blk >> 7) * DD * HWV
                            + (size_t)tid * HWV + (blk & 127) * TOKTILE;
        const float4 xa0 = *reinterpret_cast<const float4*>(xr);
        const float4 xa1 = *reinterpret_cast<const float4*>(xr + 4);
        sx[0*DD + 4*(gA ^ 0) + kA] = xa0.x;
        sx[1*DD + 4*(gA ^ 0) + kA] = xa0.y;
        sx[2*DD + 4*(gA ^ 1) + kA] = xa0.z;
        sx[3*DD + 4*(gA ^ 1) + kA] = xa0.w;
        sx[4*DD + 4*(gA ^ 2) + kA] = xa1.x;
        sx[5*DD + 4*(gA ^ 2) + kA] = xa1.y;
        sx[6*DD + 4*(gA ^ 3) + kA] = xa1.z;
        sx[7*DD + 4*(gA ^ 3) + kA] = xa1.w;
    }
    __syncthreads();

    int p = 0;
    for (int t = blk; t < NTILES; t += NBLK) {
        const int nxt = t + NBLK;
        const int t0  = t * TOKTILE;

        // ---- issue mu/lv loads (consumed first in compute) ----
        const float* mup = mu + (size_t)(t0 + sub * 2) * DD + 4 * dg;
        const float* lvp = lv + (size_t)(t0 + sub * 2) * DD + 4 * dg;
        const float4 m0 = *reinterpret_cast<const float4*>(mup);
        const float4 m1 = *reinterpret_cast<const float4*>(mup + DD);
        const float4 l0 = *reinterpret_cast<const float4*>(lvp);
        const float4 l1 = *reinterpret_cast<const float4*>(lvp + DD);

        // ---- issue next-tile x loads (latency hidden under compute) ----
        float4 xn0, xn1;
        if (nxt < NTILES) {
            const float* xr = x + (size_t)(nxt >> 7) * DD * HWV
                                + (size_t)tid * HWV + (nxt & 127) * TOKTILE;
            xn0 = *reinterpret_cast<const float4*>(xr);
            xn1 = *reinterpret_cast<const float4*>(xr + 4);
        }

        // ---- compute on current buffer ----
        {
            const float* cb = sx + p * TILEF;
            #pragma unroll
            for (int j = 0; j < 2; j++) {
                const int ts = sub * 2 + j;
                const float4 xv = *reinterpret_cast<const float4*>(
                    &cb[ts * DD + 4 * (dg ^ ((ts >> 1) & 7))]);
                const float4 mm4 = (j == 0) ? m0 : m1;
                const float4 ll4 = (j == 0) ? l0 : l1;
                float mm[4] = {mm4.x, mm4.y, mm4.z, mm4.w};
                float ll[4] = {ll4.x, ll4.y, ll4.z, ll4.w};
                float xx[4] = {xv.x, xv.y, xv.z, xv.w};
                #pragma unroll
                for (int k = 0; k < 4; k++) {
                    float iv = __expf(-ll[k]);
                    a_sinv[k] += iv;
                    a_smui[k] += mm[k] * iv;
                    a_s1[k]   += xx[k];
                    a_s2[k]   += xx[k] * xx[k];
                    a_br      += (xx[k] - 2.0f * mm[k]) * xx[k] * iv;
                }
            }
        }

        // ---- stage next tile into the other buffer ----
        if (nxt < NTILES) {
            float* sb = sx + (p ^ 1) * TILEF;
            sb[0*DD + 4*(gA ^ 0) + kA] = xn0.x;
            sb[1*DD + 4*(gA ^ 0) + kA] = xn0.y;
            sb[2*DD + 4*(gA ^ 1) + kA] = xn0.z;
            sb[3*DD + 4*(gA ^ 1) + kA] = xn0.w;
            sb[4*DD + 4*(gA ^ 2) + kA] = xn1.x;
            sb[5*DD + 4*(gA ^ 2) + kA] = xn1.y;
            sb[6*DD + 4*(gA ^ 3) + kA] = xn1.z;
            sb[7*DD + 4*(gA ^ 3) + kA] = xn1.w;
        }
        __syncthreads();
        p ^= 1;
    }

    // ---- cross-sub combine via SMEM, then transposed global write ----
    #pragma unroll
    for (int k = 0; k < 4; k++) {
        int base = (sub * 128 + dg) * 16 + k * 4;
        sx[base + 0] = a_sinv[k];
        sx[base + 1] = a_smui[k];
        sx[base + 2] = a_s1[k];
        sx[base + 3] = a_s2[k];
    }
    __syncthreads();
    {
        const int d   = tid;
        const int dg2 = d >> 2, kk = d & 3;
        float4 acc = make_float4(0.f, 0.f, 0.f, 0.f);
        #pragma unroll
        for (int sb = 0; sb < 4; sb++) {
            int base = (sb * 128 + dg2) * 16 + kk * 4;
            acc.x += sx[base + 0];
            acc.y += sx[base + 1];
            acc.z += sx[base + 2];
            acc.w += sx[base + 3];
        }
        // one strided STG.128 per thread, once per kernel -> negligible
        g_part4[(size_t)d * NBP + blk] = acc;
    }
    __syncthreads();
    sx[tid] = a_br;
    __syncthreads();
    #pragma unroll
    for (int off = 256; off > 0; off >>= 1) {
        if (tid < off) sx[tid] += sx[tid + off];
        __syncthreads();
    }
    if (tid == 0) g_br[blk] = sx[0];
}

// ---------------------------------------------------------------------------
// Pass 2+3 fused: 32 blocks x 512 thr = 512 warps; warp <-> d, lane <-> blk.
// Reads are now fully coalesced (512B per warp-load). Last-finishing block
// does the final double tree-sum -> scalar. Counter self-resets for graph
// replay. Deterministic fixed-tree sums throughout.
// ---------------------------------------------------------------------------
__global__ void club_pass23(float* __restrict__ out)
{
    const int tid  = threadIdx.x;
    const int w    = tid >> 5;
    const int lane = tid & 31;
    const int d    = blockIdx.x * 16 + w;

    float4 acc = make_float4(0.f, 0.f, 0.f, 0.f);
    #pragma unroll
    for (int k = 0; k < NBP / 32; k++) {
        float4 v = g_part4[(size_t)d * NBP + k * 32 + lane];   // coalesced
        acc.x += v.x; acc.y += v.y; acc.z += v.z; acc.w += v.w;
    }
    #pragma unroll
    for (int off = 16; off > 0; off >>= 1) {
        acc.x += __shfl_xor_sync(0xFFFFFFFFu, acc.x, off);
        acc.y += __shfl_xor_sync(0xFFFFFFFFu, acc.y, off);
        acc.z += __shfl_xor_sync(0xFFFFFFFFu, acc.z, off);
        acc.w += __shfl_xor_sync(0xFFFFFFFFu, acc.w, off);
    }
    if (lane == 0) {
        double m1 = (double)acc.z / (double)NTOK;
        double m2 = (double)acc.w / (double)NTOK;
        g_cd[d] = -(m2 * (double)acc.x) + 2.0 * m1 * (double)acc.y;
        __threadfence();                       // publish before counting
    }
    __syncthreads();

    __shared__ bool amLast;
    if (tid == 0) amLast = (atomicAdd(&g_cnt, 1u) == 31u);
    __syncthreads();

    if (amLast) {
        if (tid == 0) __threadfence();
        __syncthreads();
        __shared__ double sd[512];
        double v = __ldcg(&g_cd[tid]);
        if (tid < NBLK) v += (double)__ldcg(&g_br[tid]);
        sd[tid] = v;
        __syncthreads();
        #pragma unroll
        for (int off = 256; off > 0; off >>= 1) {
            if (tid < off) sd[tid] += sd[tid + off];
            __syncthreads();
        }
        if (tid == 0) {
            out[0] = (float)(-0.5 / (double)NTOK * sd[0]);
            g_cnt = 0;                         // reset for next graph replay
        }
    }
}

// ---------------------------------------------------------------------------
extern "C" void kernel_launch(void* const* d_in, const int* in_sizes, int n_in,
                              void* d_out, int out_size)
{
    (void)in_sizes; (void)n_in; (void)out_size;
    const float* x  = (const float*)d_in[0];
    const float* mu = (const float*)d_in[1];
    const float* lv = (const float*)d_in[2];
    float* out = (float*)d_out;

    club_pass1<<<NBLK, TPB>>>(x, mu, lv);
    club_pass23<<<32, TPB>>>(out);
}